// round 8
// baseline (speedup 1.0000x reference)
#include <cuda_runtime.h>
#include <cstdint>

// ============================================================================
// NNLS via normal equations, FFMA2 (f32x2) unified-lane scheme.
//   Per warp: rows r = w + 8k of a 64-row tile. 32 lanes = 29 jobs:
//     jobs 0..19 : G upper-triangle 8x4 tiles (i0 in {0,8,16,24}, j0 mult 4,
//                  kept iff j0+3 >= i0)
//     jobs 20..23: c[i][m] tiles (b = y-dup pairs)
//     jobs 24..27: colsum (b = ones-dup pairs)
//     job  28    : ysum + valid-count (a = y-chunk)
//     jobs 29..31: idle
//   b-operands come from a pre-duplicated pair array (no dup movs in loop).
//   Then tiny projected-gradient QP solve (G ~ N*I, kappa ~ 1.02).
// ============================================================================

#define TPB 256
#define NCTA 296
#define PGD_ITERS 48

// ACC: [0..1023] G[i][j] (triangle-covered entries), [1024..1151] c[i][m],
//      [1152..1183] colsum, [1184..1187] ysum, [1188] count
__device__ float ACC[1200];

// job tables: aoff doubles as i0 (kinds 0..2), boff doubles as j0 (kind 0)
__device__ const int JT_aoff[32] = {
    0,0,0,0,0,0,0,0,  8,8,8,8,8,8,  16,16,16,16,  24,24,
    0,8,16,24,  0,8,16,24,  32,  0,0,0 };
__device__ const int JT_boff[32] = {
    0,4,8,12,16,20,24,28,  8,12,16,20,24,28,  16,20,24,28,  24,28,
    32,32,32,32,  36,36,36,36,  36,  0,0,0 };
__device__ const int JT_kind[32] = {
    0,0,0,0,0,0,0,0, 0,0,0,0,0,0, 0,0,0,0, 0,0,
    1,1,1,1, 2,2,2,2, 3, 4,4,4 };

// dynamic smem layout (bytes):
//   araw[2]: 64 rows x 40 floats  (x0..31, y0..3, valid, 0,0,0)   2 x 10240
//   bdup[2]: 64 rows x 40 u64 pairs (xdup 0..31, ydup 32..35, ones 36..39)
#define ARAW(p) ((p) * 10240)
#define BDUP(p) (20480 + (p) * 20480)
#define SMEMSZ  61440

typedef unsigned long long u64;

static __device__ __forceinline__ void ffma2(u64& d, u64 a, u64 b) {
    asm("fma.rn.f32x2 %0, %1, %2, %0;" : "+l"(d) : "l"(a), "l"(b));
}
static __device__ __forceinline__ u64 dup2(float x) {
    u64 r; unsigned u = __float_as_uint(x);
    asm("mov.b64 %0, {%1, %1};" : "=l"(r) : "r"(u));
    return r;
}
static __device__ __forceinline__ void unpack2(u64 v, float& lo, float& hi) {
    unsigned a, b;
    asm("mov.b64 {%0, %1}, %2;" : "=r"(a), "=r"(b) : "l"(v));
    lo = __uint_as_float(a);
    hi = __uint_as_float(b);
}

__global__ void zero_acc_kernel() {
    int t = blockIdx.x * blockDim.x + threadIdx.x;
    if (t < 1200) ACC[t] = 0.0f;
}

// ---------------------------------------------------------------------------
__global__ __launch_bounds__(TPB, 2) void gram_kernel(
    const float* __restrict__ X, const float* __restrict__ Y,
    int N, int ntiles)
{
    extern __shared__ char smem[];
    const int tid = threadIdx.x;
    const int w   = tid >> 5;
    const int l   = tid & 31;

    const int a_off = JT_aoff[l];
    const int b_off = JT_boff[l];

    u64 acc[4][4];
#pragma unroll
    for (int p = 0; p < 4; p++)
#pragma unroll
        for (int q = 0; q < 4; q++) acc[p][q] = 0ull;

    // ones-dup pairs (constant across tiles): bdup[*][r][36..39] = (1,1)
    if (tid < 128) {
        int p = tid >> 6, r = tid & 63;
        u64* b = (u64*)(smem + BDUP(p)) + r * 40 + 36;
        ulonglong2 o; o.x = dup2(1.0f); o.y = dup2(1.0f);
        *(ulonglong2*)(b)     = o;
        *(ulonglong2*)(b + 2) = o;
    }

    const int bx = blockIdx.x;
    const int nloc = (ntiles > bx) ? (ntiles - 1 - bx) / (int)gridDim.x + 1 : 0;

    // staging: 4 threads per row; xrow = tid>>2, cols xcg..xcg+7
    const int xrow   = tid >> 2;
    const int xcg    = (tid & 3) * 8;
    const int leader = ((tid & 3) == 0);
    float4 xa, xb, yv;
    float vflag = 0.f;
    const float4 z4 = make_float4(0.f, 0.f, 0.f, 0.f);

    auto prefetch = [&](int i) {
        long long g = (long long)bx + (long long)i * gridDim.x;
        long long r = g * 64 + xrow;
        int valid = (r < (long long)N);
        if (valid) {
            const float4* px = (const float4*)(X + r * 32 + xcg);
            xa = px[0]; xb = px[1];
        } else { xa = z4; xb = z4; }
        if (leader) {
            yv = valid ? ((const float4*)Y)[r] : z4;
            vflag = valid ? 1.0f : 0.0f;
        }
    };

    auto store = [&](int p) {
        float* ar = (float*)(smem + ARAW(p)) + xrow * 40 + xcg;
        *(float4*)(ar)     = xa;
        *(float4*)(ar + 4) = xb;
        u64* br = (u64*)(smem + BDUP(p)) + xrow * 40 + xcg;
        ulonglong2 d;
        d.x = dup2(xa.x); d.y = dup2(xa.y); *(ulonglong2*)(br)     = d;
        d.x = dup2(xa.z); d.y = dup2(xa.w); *(ulonglong2*)(br + 2) = d;
        d.x = dup2(xb.x); d.y = dup2(xb.y); *(ulonglong2*)(br + 4) = d;
        d.x = dup2(xb.z); d.y = dup2(xb.w); *(ulonglong2*)(br + 6) = d;
        if (leader) {
            float* ay = (float*)(smem + ARAW(p)) + xrow * 40 + 32;
            *(float4*)(ay)     = yv;
            *(float4*)(ay + 4) = make_float4(vflag, 0.f, 0.f, 0.f);
            u64* by = (u64*)(smem + BDUP(p)) + xrow * 40 + 32;
            ulonglong2 dy;
            dy.x = dup2(yv.x); dy.y = dup2(yv.y); *(ulonglong2*)(by)     = dy;
            dy.x = dup2(yv.z); dy.y = dup2(yv.w); *(ulonglong2*)(by + 2) = dy;
        }
    };

    if (nloc > 0) { prefetch(0); store(0); }
    __syncthreads();

    for (int i = 0; i < nloc; i++) {
        const int p = i & 1;
        if (i + 1 < nloc) prefetch(i + 1);

        const float* abase = (const float*)(smem + ARAW(p)) + w * 40 + a_off;
        const u64*   bbase = (const u64*)(smem + BDUP(p)) + w * 40 + b_off;
#pragma unroll
        for (int k = 0; k < 8; k++) {
            const float* ar = abase + k * 320;
            ulonglong2 a01 = *(const ulonglong2*)(ar);
            ulonglong2 a23 = *(const ulonglong2*)(ar + 4);
            const ulonglong2* br = (const ulonglong2*)(bbase + k * 320);
            ulonglong2 b01 = br[0];
            ulonglong2 b23 = br[1];
            u64 ap[4] = {a01.x, a01.y, a23.x, a23.y};
            u64 bp[4] = {b01.x, b01.y, b23.x, b23.y};
#pragma unroll
            for (int pp = 0; pp < 4; pp++)
#pragma unroll
                for (int q = 0; q < 4; q++) ffma2(acc[pp][q], ap[pp], bp[q]);
        }

        if (i + 1 < nloc) store(p ^ 1);
        __syncthreads();
    }

    // ---- epilogue: stash per-lane accs, 8-warp reduce, atomic scatter ----
    __syncthreads();
    u64* epi = (u64*)smem;                      // 8*32*16 u64 = 32 KB
    u64* mine = epi + (w * 32 + l) * 16;
#pragma unroll
    for (int t = 0; t < 16; t++) mine[t] = acc[t >> 2][t & 3];
    __syncthreads();

    for (int s = tid; s < 512; s += TPB) {
        const int l2 = s >> 4, t = s & 15;
        const int kind = JT_kind[l2];
        if (kind == 4) continue;
        float lo = 0.f, hi = 0.f;
#pragma unroll
        for (int ww = 0; ww < 8; ww++) {
            float a, b;
            unpack2(epi[(ww * 32 + l2) * 16 + t], a, b);
            lo += a; hi += b;
        }
        const int i0 = JT_aoff[l2], j0 = JT_boff[l2];
        const int pp = t >> 2, qq = t & 3;
        if (kind == 0) {
            const int ii = i0 + 2 * pp, jj = j0 + qq;
            atomicAdd(&ACC[ii * 32 + jj], lo);
            atomicAdd(&ACC[(ii + 1) * 32 + jj], hi);
        } else if (kind == 1) {
            const int ii = i0 + 2 * pp;
            atomicAdd(&ACC[1024 + ii * 4 + qq], lo);
            atomicAdd(&ACC[1024 + (ii + 1) * 4 + qq], hi);
        } else if (kind == 2) {
            if (qq == 0) {
                const int ii = i0 + 2 * pp;
                atomicAdd(&ACC[1152 + ii], lo);
                atomicAdd(&ACC[1153 + ii], hi);
            }
        } else {  // kind 3: ysum / count
            if (qq == 0) {
                if (pp < 2) {
                    atomicAdd(&ACC[1184 + 2 * pp], lo);
                    atomicAdd(&ACC[1185 + 2 * pp], hi);
                } else if (pp == 2) {
                    atomicAdd(&ACC[1188], lo);
                }
            }
        }
    }
}

// ---------------------------------------------------------------------------
__global__ __launch_bounds__(256) void solve_kernel(float* __restrict__ out, float Nf)
{
    __shared__ float G[33 * 33];
    __shared__ float c[132];
    __shared__ float Z[132];
    __shared__ float rowsum[33];
    __shared__ float stepSh;

    const int tid = threadIdx.x;
    for (int e = tid; e < 33 * 33; e += 256) {
        int i = e / 33, j = e % 33;
        float v;
        if (i < 32 && j < 32)
            v = ((j | 3) >= (i & ~7)) ? ACC[i * 32 + j] : ACC[j * 32 + i];
        else if (i < 32)      v = ACC[1152 + i];
        else if (j < 32)      v = ACC[1152 + j];
        else                  v = Nf;
        G[e] = v;
    }
    if (tid < 132) {
        int i = tid >> 2, m = tid & 3;
        c[tid] = (i < 32) ? ACC[1024 + tid] : ACC[1184 + m];
        Z[tid] = 0.0f;
    }
    __syncthreads();

    if (tid < 33) {
        float s = 0.f;
        for (int j = 0; j < 33; j++) s += fabsf(G[tid * 33 + j]);
        rowsum[tid] = s;
    }
    __syncthreads();
    if (tid == 0) {
        float L = 0.f;
        for (int i = 0; i < 33; i++) L = fmaxf(L, rowsum[i]);
        stepSh = 1.0f / L;
    }
    __syncthreads();
    const float step = stepSh;

    const int i = tid >> 2, m = tid & 3;
    for (int it = 0; it < PGD_ITERS; it++) {
        float zn = 0.f;
        if (tid < 132) {
            float dot = 0.f;
#pragma unroll
            for (int j = 0; j < 33; j++) dot += G[i * 33 + j] * Z[j * 4 + m];
            zn = Z[tid] - step * (dot - c[tid]);
            if (i < 32) zn = fmaxf(zn, 0.0f);
        }
        __syncthreads();
        if (tid < 132) Z[tid] = zn;
        __syncthreads();
    }
    if (tid < 128) out[tid] = Z[tid];
}

// ---------------------------------------------------------------------------
extern "C" void kernel_launch(void* const* d_in, const int* in_sizes, int n_in,
                              void* d_out, int out_size)
{
    const float* X = (const float*)d_in[0];
    const float* Y = (const float*)d_in[1];
    const int N = in_sizes[0] / 32;
    const int ntiles = (N + 63) / 64;

    cudaFuncSetAttribute(gram_kernel,
                         cudaFuncAttributeMaxDynamicSharedMemorySize, SMEMSZ);

    zero_acc_kernel<<<5, 256>>>();
    gram_kernel<<<NCTA, TPB, SMEMSZ>>>(X, Y, N, ntiles);
    solve_kernel<<<1, 256>>>((float*)d_out, (float)N);
}

// round 9
// speedup vs baseline: 1.8013x; 1.8013x over previous
#include <cuda_runtime.h>
#include <cstdint>

// ============================================================================
// NNLS via normal equations, FFMA2 (f32x2), triangle lane-job scheme.
// Staged rows (stride 40): [x0..x31 | y0..y3 | valid | 0 0 0]
// Per warp: rows r = w + 8k. 32 lanes = 29 jobs, uniform instruction stream:
//   kind0 (20): G upper-triangle 8x4 tiles  (a=x[i0..i0+7], b=x[j0..j0+3])
//   kind1 (4) : c tiles                     (b = y quad at col 32)
//   kind2 (4) : colsum tiles                (b = valid quad at col 36)
//   kind3 (1) : ysum + count                (a = cols 32..39)
//   kind4 (3) : idle duplicates (ignored)
// Staging = R4's cp.async double buffer (no register prefetch, no dup array).
// Then tiny projected-gradient QP solve (G ~ N*I, kappa ~ 1.02).
// ============================================================================

#define TPB 256
#define NCTA 296
#define PGD_ITERS 48

// ACC: [0..1023] G tiles, [1024..1151] c[i][m], [1152..1183] colsum,
//      [1184..1187] ysum, [1188] count
__device__ float ACC[1200];

__constant__ int JT_aoff[32] = {
    0,0,0,0,0,0,0,0,  8,8,8,8,8,8,  16,16,16,16,  24,24,
    0,8,16,24,  0,8,16,24,  32,  0,0,0 };
__constant__ int JT_boff[32] = {
    0,4,8,12,16,20,24,28,  8,12,16,20,24,28,  16,20,24,28,  24,28,
    32,32,32,32,  36,36,36,36,  36,  36,36,36 };
__constant__ int JT_kind[32] = {
    0,0,0,0,0,0,0,0, 0,0,0,0,0,0, 0,0,0,0, 0,0,
    1,1,1,1, 2,2,2,2, 3, 4,4,4 };

// dynamic smem: buf[2]: 64 rows x 40 floats = 2 x 10240 B; epilogue reuses it
#define BUFB 10240
#define SMEMSZ 40960   // max(2*10240, 8*32*16*8 epilogue = 32768) -> 40960 safe

typedef unsigned long long u64;

static __device__ __forceinline__ uint32_t s2u(const void* p) {
    uint32_t a;
    asm("{ .reg .u64 t; cvta.to.shared.u64 t, %1; cvt.u32.u64 %0, t; }"
        : "=r"(a) : "l"(p));
    return a;
}
#define CP16(dst, src) \
    asm volatile("cp.async.cg.shared.global [%0], [%1], 16;" :: "r"(dst), "l"(src) : "memory")
#define CP_COMMIT() asm volatile("cp.async.commit_group;" ::: "memory")
#define CP_WAIT1()  asm volatile("cp.async.wait_group 1;" ::: "memory")
#define CP_WAIT0()  asm volatile("cp.async.wait_group 0;" ::: "memory")

static __device__ __forceinline__ void ffma2(u64& d, u64 a, u64 b) {
    asm("fma.rn.f32x2 %0, %1, %2, %0;" : "+l"(d) : "l"(a), "l"(b));
}
static __device__ __forceinline__ u64 dup2(float x) {
    u64 r; unsigned u = __float_as_uint(x);
    asm("mov.b64 %0, {%1, %1};" : "=l"(r) : "r"(u));
    return r;
}
static __device__ __forceinline__ void unpack2(u64 v, float& lo, float& hi) {
    unsigned a, b;
    asm("mov.b64 {%0, %1}, %2;" : "=r"(a), "=r"(b) : "l"(v));
    lo = __uint_as_float(a);
    hi = __uint_as_float(b);
}

__global__ void zero_acc_kernel() {
    int t = blockIdx.x * blockDim.x + threadIdx.x;
    if (t < 1200) ACC[t] = 0.0f;
}

// ---------------------------------------------------------------------------
__global__ __launch_bounds__(TPB, 2) void gram_kernel(
    const float* __restrict__ X, const float* __restrict__ Y,
    int N, int ntiles)
{
    extern __shared__ char smem[];
    const uint32_t sb = s2u(smem);
    const int tid = threadIdx.x;
    const int w   = tid >> 5;
    const int l   = tid & 31;

    const int a_off = JT_aoff[l];
    const int b_off = JT_boff[l];

    u64 acc[4][4];
#pragma unroll
    for (int p = 0; p < 4; p++)
#pragma unroll
        for (int q = 0; q < 4; q++) acc[p][q] = 0ull;

    const int bx = blockIdx.x;
    const int nloc = (ntiles > bx) ? (ntiles - 1 - bx) / (int)gridDim.x + 1 : 0;

    // staging: 4 threads per row; xrow = tid>>2, quad xq = tid&3 -> cols 8xq..8xq+7
    const int xrow = tid >> 2;
    const int xq   = tid & 3;

    auto stage = [&](int i) {
        const int p = i & 1;
        long long g = (long long)bx + (long long)i * gridDim.x;
        long long r = g * 64 + xrow;
        const int valid = (r < (long long)N);
        float* rowp = (float*)(smem + p * BUFB) + xrow * 40;
        uint32_t dst = sb + p * BUFB + xrow * 160 + xq * 32;
        if (valid) {
            const float* src = X + r * 32 + xq * 8;
            CP16(dst, src);
            CP16(dst + 16, src + 4);
        } else {
            const float4 z4 = make_float4(0.f, 0.f, 0.f, 0.f);
            *(float4*)(rowp + xq * 8)     = z4;
            *(float4*)(rowp + xq * 8 + 4) = z4;
        }
        if (xq == 0) {
            if (valid) CP16(sb + p * BUFB + xrow * 160 + 128, Y + r * 4);
            else *(float4*)(rowp + 32) = make_float4(0.f, 0.f, 0.f, 0.f);
            *(float4*)(rowp + 36) = make_float4(valid ? 1.0f : 0.0f, 0.f, 0.f, 0.f);
        }
        CP_COMMIT();
    };

    if (nloc > 0) stage(0);

    for (int i = 0; i < nloc; i++) {
        const int p = i & 1;
        if (i + 1 < nloc) { stage(i + 1); CP_WAIT1(); } else { CP_WAIT0(); }
        __syncthreads();

        const float* arow = (const float*)(smem + p * BUFB) + w * 40 + a_off;
        const float* brow = (const float*)(smem + p * BUFB) + w * 40 + b_off;
#pragma unroll
        for (int k = 0; k < 8; k++) {
            ulonglong2 a01 = *(const ulonglong2*)(arow + k * 320);
            ulonglong2 a23 = *(const ulonglong2*)(arow + k * 320 + 4);
            float4     bv  = *(const float4*)(brow + k * 320);
            u64 ap[4] = {a01.x, a01.y, a23.x, a23.y};
            u64 bd[4] = {dup2(bv.x), dup2(bv.y), dup2(bv.z), dup2(bv.w)};
#pragma unroll
            for (int pp = 0; pp < 4; pp++)
#pragma unroll
                for (int q = 0; q < 4; q++) ffma2(acc[pp][q], ap[pp], bd[q]);
        }
        __syncthreads();
    }

    // ---- epilogue: stash per-lane accs, 8-warp reduce, atomic scatter ----
    u64* epi = (u64*)smem;
    u64* mine = epi + (w * 32 + l) * 16;
#pragma unroll
    for (int t = 0; t < 16; t++) mine[t] = acc[t >> 2][t & 3];
    __syncthreads();

    for (int s = tid; s < 512; s += TPB) {
        const int l2 = s >> 4, t = s & 15;
        const int kind = JT_kind[l2];
        if (kind == 4) continue;
        const int pp = t >> 2, qq = t & 3;
        if (kind >= 2 && qq != 0) continue;
        float lo = 0.f, hi = 0.f;
#pragma unroll
        for (int ww = 0; ww < 8; ww++) {
            float a, b;
            unpack2(epi[(ww * 32 + l2) * 16 + t], a, b);
            lo += a; hi += b;
        }
        const int i0 = JT_aoff[l2], j0 = JT_boff[l2];
        const int ii = i0 + 2 * pp;
        if (kind == 0) {
            atomicAdd(&ACC[ii * 32 + j0 + qq], lo);
            atomicAdd(&ACC[(ii + 1) * 32 + j0 + qq], hi);
        } else if (kind == 1) {
            atomicAdd(&ACC[1024 + ii * 4 + qq], lo);
            atomicAdd(&ACC[1024 + (ii + 1) * 4 + qq], hi);
        } else if (kind == 2) {
            atomicAdd(&ACC[1152 + ii], lo);
            atomicAdd(&ACC[1153 + ii], hi);
        } else {  // kind 3: a = (y0,y1)(y2,y3)(valid,0)(0,0), b = valid
            if (pp < 2) {
                atomicAdd(&ACC[1184 + 2 * pp], lo);
                atomicAdd(&ACC[1185 + 2 * pp], hi);
            } else if (pp == 2) {
                atomicAdd(&ACC[1188], lo);   // count = sum valid^2
            }
        }
    }
}

// ---------------------------------------------------------------------------
__global__ __launch_bounds__(256) void solve_kernel(float* __restrict__ out, float Nf)
{
    __shared__ float G[33 * 33];
    __shared__ float c[132];
    __shared__ float Z[132];
    __shared__ float rowsum[33];
    __shared__ float stepSh;

    const int tid = threadIdx.x;
    // triangle coverage predicate: tile (i>>3, j>>2) computed iff (j|3) >= (i&~7)
    for (int e = tid; e < 33 * 33; e += 256) {
        int i = e / 33, j = e % 33;
        float v;
        if (i < 32 && j < 32)
            v = ((j | 3) >= (i & ~7)) ? ACC[i * 32 + j] : ACC[j * 32 + i];
        else if (i < 32)      v = ACC[1152 + i];
        else if (j < 32)      v = ACC[1152 + j];
        else                  v = ACC[1188];
        G[e] = v;
    }
    if (tid < 132) {
        int i = tid >> 2, m = tid & 3;
        c[tid] = (i < 32) ? ACC[1024 + tid] : ACC[1184 + m];
        Z[tid] = 0.0f;
    }
    __syncthreads();

    if (tid < 33) {
        float s = 0.f;
        for (int j = 0; j < 33; j++) s += fabsf(G[tid * 33 + j]);
        rowsum[tid] = s;
    }
    __syncthreads();
    if (tid == 0) {
        float L = 0.f;
        for (int i = 0; i < 33; i++) L = fmaxf(L, rowsum[i]);
        stepSh = 1.0f / L;
    }
    __syncthreads();
    const float step = stepSh;

    const int i = tid >> 2, m = tid & 3;
    for (int it = 0; it < PGD_ITERS; it++) {
        float zn = 0.f;
        if (tid < 132) {
            float dot = 0.f;
#pragma unroll
            for (int j = 0; j < 33; j++) dot += G[i * 33 + j] * Z[j * 4 + m];
            zn = Z[tid] - step * (dot - c[tid]);
            if (i < 32) zn = fmaxf(zn, 0.0f);
        }
        __syncthreads();
        if (tid < 132) Z[tid] = zn;
        __syncthreads();
    }
    if (tid < 128) out[tid] = Z[tid];
}

// ---------------------------------------------------------------------------
extern "C" void kernel_launch(void* const* d_in, const int* in_sizes, int n_in,
                              void* d_out, int out_size)
{
    const float* X = (const float*)d_in[0];
    const float* Y = (const float*)d_in[1];
    const int N = in_sizes[0] / 32;
    const int ntiles = (N + 63) / 64;

    cudaFuncSetAttribute(gram_kernel,
                         cudaFuncAttributeMaxDynamicSharedMemorySize, SMEMSZ);

    zero_acc_kernel<<<5, 256>>>();
    gram_kernel<<<NCTA, TPB, SMEMSZ>>>(X, Y, N, ntiles);
    solve_kernel<<<1, 256>>>((float*)d_out, (float)N);
}

// round 10
// speedup vs baseline: 1.8802x; 1.0438x over previous
#include <cuda_runtime.h>
#include <cstdint>

// ============================================================================
// NNLS via normal equations, FFMA2 (f32x2), triangle lane-jobs with
// BANK-ALIGNED layout (single-variable experiment vs R9):
//   Xbuf rows: 64 x 32 floats (128B-aligned rows, stride 32)
//   Ybuf rows: 64 x 8 floats  [y0 y1 y2 y3 v 0 0 0] (32B rows)
// Per warp: rows r = w + 8k. 29 lane jobs, uniform stream
//   (2x LDS.128 a-pairs, 1x LDS.128 b-quad, 4 dup, 16 FFMA2):
//   kind0 (20): G upper-triangle 8x4 tiles     (a,b from Xbuf)
//   kind1 (4) : c tiles        (b = y quad,  Ybuf+0)
//   kind2 (4) : colsum tiles   (b = valid quad, Ybuf+4)
//   kind3 (1) : ysum + count   (a = Ybuf row, b = Ybuf+4)
// Then tiny projected-gradient QP solve (G ~ N*I, kappa ~ 1.02).
// ============================================================================

#define TPB 256
#define NCTA 296
#define PGD_ITERS 48

// ACC: [0..1023] G tiles, [1024..1151] c[i][m], [1152..1183] colsum,
//      [1184..1187] ysum, [1188] count
__device__ float ACC[1200];

__constant__ int JT_aoff[32] = {
    0,0,0,0,0,0,0,0,  8,8,8,8,8,8,  16,16,16,16,  24,24,
    0,8,16,24,  0,8,16,24,  32,  0,0,0 };
__constant__ int JT_boff[32] = {
    0,4,8,12,16,20,24,28,  8,12,16,20,24,28,  16,20,24,28,  24,28,
    32,32,32,32,  36,36,36,36,  36,  36,36,36 };
__constant__ int JT_kind[32] = {
    0,0,0,0,0,0,0,0, 0,0,0,0,0,0, 0,0,0,0, 0,0,
    1,1,1,1, 2,2,2,2, 3, 4,4,4 };

// smem: Xbuf[2] 8192 B @0, Ybuf[2] 2048 B @16384; epilogue overlays (32768 B)
#define XB(p) ((p) * 8192)
#define YB(p) (16384 + (p) * 2048)
#define SMEMSZ 32768

typedef unsigned long long u64;

static __device__ __forceinline__ uint32_t s2u(const void* p) {
    uint32_t a;
    asm("{ .reg .u64 t; cvta.to.shared.u64 t, %1; cvt.u32.u64 %0, t; }"
        : "=r"(a) : "l"(p));
    return a;
}
#define CP16(dst, src) \
    asm volatile("cp.async.cg.shared.global [%0], [%1], 16;" :: "r"(dst), "l"(src) : "memory")
#define CP_COMMIT() asm volatile("cp.async.commit_group;" ::: "memory")
#define CP_WAIT1()  asm volatile("cp.async.wait_group 1;" ::: "memory")
#define CP_WAIT0()  asm volatile("cp.async.wait_group 0;" ::: "memory")

static __device__ __forceinline__ void ffma2(u64& d, u64 a, u64 b) {
    asm("fma.rn.f32x2 %0, %1, %2, %0;" : "+l"(d) : "l"(a), "l"(b));
}
static __device__ __forceinline__ u64 dup2(float x) {
    u64 r; unsigned u = __float_as_uint(x);
    asm("mov.b64 %0, {%1, %1};" : "=l"(r) : "r"(u));
    return r;
}
static __device__ __forceinline__ void unpack2(u64 v, float& lo, float& hi) {
    unsigned a, b;
    asm("mov.b64 {%0, %1}, %2;" : "=r"(a), "=r"(b) : "l"(v));
    lo = __uint_as_float(a);
    hi = __uint_as_float(b);
}

__global__ void zero_acc_kernel() {
    int t = blockIdx.x * blockDim.x + threadIdx.x;
    if (t < 1200) ACC[t] = 0.0f;
}

// ---------------------------------------------------------------------------
__global__ __launch_bounds__(TPB, 2) void gram_kernel(
    const float* __restrict__ X, const float* __restrict__ Y,
    int N, int ntiles)
{
    extern __shared__ char smem[];
    const uint32_t sb = s2u(smem);
    const int tid = threadIdx.x;
    const int w   = tid >> 5;
    const int l   = tid & 31;

    const int a_off = JT_aoff[l];
    const int b_off = JT_boff[l];
    // per-lane source select: offsets >= 32 live in the Ybuf region
    const int a_inY = (a_off >= 32);
    const int b_inY = (b_off >= 32);
    const int astep = a_inY ? 64 : 256;   // floats per k-step (8 rows)
    const int bstep = b_inY ? 64 : 256;
    const int a_rel = a_inY ? (w * 8 + (a_off - 32)) : (w * 32 + a_off);
    const int b_rel = b_inY ? (w * 8 + (b_off - 32)) : (w * 32 + b_off);

    u64 acc[4][4];
#pragma unroll
    for (int p = 0; p < 4; p++)
#pragma unroll
        for (int q = 0; q < 4; q++) acc[p][q] = 0ull;

    const int bx = blockIdx.x;
    const int nloc = (ntiles > bx) ? (ntiles - 1 - bx) / (int)gridDim.x + 1 : 0;

    // staging: 4 threads per row; xrow = tid>>2, quad xq = tid&3
    const int xrow = tid >> 2;
    const int xq   = tid & 3;

    auto stage = [&](int i) {
        const int p = i & 1;
        long long g = (long long)bx + (long long)i * gridDim.x;
        long long r = g * 64 + xrow;
        const int valid = (r < (long long)N);
        uint32_t xdst = sb + XB(p) + xrow * 128 + xq * 32;
        if (valid) {
            const float* src = X + r * 32 + xq * 8;
            CP16(xdst, src);
            CP16(xdst + 16, src + 4);
        } else {
            float* rowp = (float*)(smem + XB(p)) + xrow * 32 + xq * 8;
            const float4 z4 = make_float4(0.f, 0.f, 0.f, 0.f);
            *(float4*)(rowp)     = z4;
            *(float4*)(rowp + 4) = z4;
        }
        if (xq == 0) {
            float* yrow = (float*)(smem + YB(p)) + xrow * 8;
            if (valid) CP16(sb + YB(p) + xrow * 32, Y + r * 4);
            else *(float4*)(yrow) = make_float4(0.f, 0.f, 0.f, 0.f);
            *(float4*)(yrow + 4) = make_float4(valid ? 1.0f : 0.0f, 0.f, 0.f, 0.f);
        }
        CP_COMMIT();
    };

    if (nloc > 0) stage(0);

    for (int i = 0; i < nloc; i++) {
        const int p = i & 1;
        if (i + 1 < nloc) { stage(i + 1); CP_WAIT1(); } else { CP_WAIT0(); }
        __syncthreads();

        const float* base = (const float*)(smem + (p ? 8192 : 0));
        // Ybuf(p) = base + (16384 - p*8192 + p*2048)/4 ... compute directly:
        const float* ab = a_inY ? (const float*)(smem + YB(p)) + (a_rel)
                                : (const float*)(smem + XB(p)) + (a_rel);
        const float* bb = b_inY ? (const float*)(smem + YB(p)) + (b_rel)
                                : (const float*)(smem + XB(p)) + (b_rel);
        (void)base;
#pragma unroll
        for (int k = 0; k < 8; k++) {
            ulonglong2 a01 = *(const ulonglong2*)(ab + k * astep);
            ulonglong2 a23 = *(const ulonglong2*)(ab + k * astep + 4);
            float4     bv  = *(const float4*)(bb + k * bstep);
            u64 ap[4] = {a01.x, a01.y, a23.x, a23.y};
            u64 bd[4] = {dup2(bv.x), dup2(bv.y), dup2(bv.z), dup2(bv.w)};
#pragma unroll
            for (int pp = 0; pp < 4; pp++)
#pragma unroll
                for (int q = 0; q < 4; q++) ffma2(acc[pp][q], ap[pp], bd[q]);
        }
        __syncthreads();
    }

    // ---- epilogue: stash per-lane accs, 8-warp reduce, atomic scatter ----
    u64* epi = (u64*)smem;
    u64* mine = epi + (w * 32 + l) * 16;
#pragma unroll
    for (int t = 0; t < 16; t++) mine[t] = acc[t >> 2][t & 3];
    __syncthreads();

    for (int s = tid; s < 512; s += TPB) {
        const int l2 = s >> 4, t = s & 15;
        const int kind = JT_kind[l2];
        if (kind == 4) continue;
        const int pp = t >> 2, qq = t & 3;
        if (kind >= 2 && qq != 0) continue;
        float lo = 0.f, hi = 0.f;
#pragma unroll
        for (int ww = 0; ww < 8; ww++) {
            float a, b;
            unpack2(epi[(ww * 32 + l2) * 16 + t], a, b);
            lo += a; hi += b;
        }
        const int i0 = JT_aoff[l2], j0 = JT_boff[l2];
        const int ii = i0 + 2 * pp;
        if (kind == 0) {
            atomicAdd(&ACC[ii * 32 + j0 + qq], lo);
            atomicAdd(&ACC[(ii + 1) * 32 + j0 + qq], hi);
        } else if (kind == 1) {
            atomicAdd(&ACC[1024 + ii * 4 + qq], lo);
            atomicAdd(&ACC[1024 + (ii + 1) * 4 + qq], hi);
        } else if (kind == 2) {
            atomicAdd(&ACC[1152 + ii], lo);
            atomicAdd(&ACC[1153 + ii], hi);
        } else {  // kind 3: a = (y0,y1)(y2,y3)(v,0)(0,0), b = (v,0,0,0)
            if (pp < 2) {
                atomicAdd(&ACC[1184 + 2 * pp], lo);
                atomicAdd(&ACC[1185 + 2 * pp], hi);
            } else if (pp == 2) {
                atomicAdd(&ACC[1188], lo);   // count = sum v*v
            }
        }
    }
}

// ---------------------------------------------------------------------------
__global__ __launch_bounds__(256) void solve_kernel(float* __restrict__ out)
{
    __shared__ float G[33 * 33];
    __shared__ float c[132];
    __shared__ float Z[132];
    __shared__ float rowsum[33];
    __shared__ float stepSh;

    const int tid = threadIdx.x;
    // triangle coverage: tile (i>>3, j>>2) computed iff (j|3) >= (i&~7)
    for (int e = tid; e < 33 * 33; e += 256) {
        int i = e / 33, j = e % 33;
        float v;
        if (i < 32 && j < 32)
            v = ((j | 3) >= (i & ~7)) ? ACC[i * 32 + j] : ACC[j * 32 + i];
        else if (i < 32)      v = ACC[1152 + i];
        else if (j < 32)      v = ACC[1152 + j];
        else                  v = ACC[1188];
        G[e] = v;
    }
    if (tid < 132) {
        int i = tid >> 2, m = tid & 3;
        c[tid] = (i < 32) ? ACC[1024 + tid] : ACC[1184 + m];
        Z[tid] = 0.0f;
    }
    __syncthreads();

    if (tid < 33) {
        float s = 0.f;
        for (int j = 0; j < 33; j++) s += fabsf(G[tid * 33 + j]);
        rowsum[tid] = s;
    }
    __syncthreads();
    if (tid == 0) {
        float L = 0.f;
        for (int i = 0; i < 33; i++) L = fmaxf(L, rowsum[i]);
        stepSh = 1.0f / L;
    }
    __syncthreads();
    const float step = stepSh;

    const int i = tid >> 2, m = tid & 3;
    for (int it = 0; it < PGD_ITERS; it++) {
        float zn = 0.f;
        if (tid < 132) {
            float dot = 0.f;
#pragma unroll
            for (int j = 0; j < 33; j++) dot += G[i * 33 + j] * Z[j * 4 + m];
            zn = Z[tid] - step * (dot - c[tid]);
            if (i < 32) zn = fmaxf(zn, 0.0f);
        }
        __syncthreads();
        if (tid < 132) Z[tid] = zn;
        __syncthreads();
    }
    if (tid < 128) out[tid] = Z[tid];
}

// ---------------------------------------------------------------------------
extern "C" void kernel_launch(void* const* d_in, const int* in_sizes, int n_in,
                              void* d_out, int out_size)
{
    const float* X = (const float*)d_in[0];
    const float* Y = (const float*)d_in[1];
    const int N = in_sizes[0] / 32;
    const int ntiles = (N + 63) / 64;

    cudaFuncSetAttribute(gram_kernel,
                         cudaFuncAttributeMaxDynamicSharedMemorySize, SMEMSZ);

    zero_acc_kernel<<<5, 256>>>();
    gram_kernel<<<NCTA, TPB, SMEMSZ>>>(X, Y, N, ntiles);
    solve_kernel<<<1, 256>>>((float*)d_out);
}